// round 1
// baseline (speedup 1.0000x reference)
#include <cuda_runtime.h>
#include <cstdint>

#define PI_F 3.14159265358979323846f

constexpr int NROWS   = 8192;
constexpr int DD      = 64;
constexpr int BAS     = 2048;
constexpr int ROWS    = 32;    // x-rows per CTA
constexpr int BK      = 32;    // basis tile
constexpr int THREADS = 256;

// scratch (allocation-free per harness rules)
__device__ float g_St[DD * BAS];   // [d][b] = eps[b][d] / (pi * lam[d])  (angle = pi * (x . St_col))
__device__ float g_WS[BAS * DD];   // [b][c] = -mat[b][c] * w_s[b]
__device__ float g_WC[BAS * DD];   // [b][c] =  mat[b][c] * w_c[b]

typedef unsigned long long u64;

__device__ __forceinline__ u64 pack2(float lo, float hi) {
  u64 r; asm("mov.b64 %0, {%1, %2};" : "=l"(r) : "f"(lo), "f"(hi)); return r;
}
__device__ __forceinline__ void unpack2(u64 a, float& lo, float& hi) {
  asm("mov.b64 {%0, %1}, %2;" : "=f"(lo), "=f"(hi) : "l"(a));
}
__device__ __forceinline__ u64 fma2(u64 a, u64 b, u64 c) {
  u64 d; asm("fma.rn.f32x2 %0, %1, %2, %3;" : "=l"(d) : "l"(a), "l"(b), "l"(c)); return d;
}

__global__ void precompute_kernel(const float* __restrict__ eps,
                                  const float* __restrict__ lam,
                                  const float* __restrict__ eta,
                                  const float* __restrict__ w) {
  int idx = blockIdx.x * blockDim.x + threadIdx.x;
  if (idx >= BAS * DD) return;
  int b = idx >> 6;
  int d = idx & 63;
  float lam_d = lam[d];
  float e     = eps[idx];
  // angle scale: sim = 2*pi*(x . eps/(2*pi*lam)) = pi * (x . eps/(pi*lam))
  g_St[d * BAS + b] = e / (PI_F * lam_d);
  float m;
  if (d < 32) {
    m = eps[b * DD + d + 32] / lam[d + 32];
  } else {
    float et = eta[0];
    m = -eps[b * DD + d - 32] / lam[d - 32] - (et * et) * (e / lam_d);
  }
  g_WS[idx] = -m * w[b];         // sign of -sin folded in
  g_WC[idx] =  m * w[BAS + b];
}

__global__ __launch_bounds__(THREADS, 2)
void ssgp_main_kernel(const float* __restrict__ x, float* __restrict__ out) {
  __shared__ float Xt[DD][ROWS + 2];    // [d][r], stride 34 floats (136B, 8B aligned)
  __shared__ float St[DD][BK];          // [d][bb], rows are 128B
  __shared__ float Pt[2 * BK][36];      // [k][r]; k<32: sin, k>=32: cos (144B rows)
  __shared__ float Wsm[2 * BK][DD];     // [k][c]; k<32: -w_s*mat, k>=32: w_c*mat

  const int tid = threadIdx.x;
  const int r0  = blockIdx.x * ROWS;

  const int ty = tid >> 4;   // 0..15 -> rows {2ty, 2ty+1}
  const int tx = tid & 15;   // 0..15 -> GEMM1 basis {2tx,2tx+1}; GEMM2 cols {4tx..4tx+3}

  // ---- Load X tile (32 rows x 64 dims), transpose into Xt[d][r] ----
  #pragma unroll
  for (int i = 0; i < 2; i++) {
    int j  = tid + i * 256;           // 0..511 float4s
    int r  = j >> 4;                  // 0..31
    int d4 = (j & 15) * 4;
    float4 v = *reinterpret_cast<const float4*>(&x[(size_t)(r0 + r) * DD + d4]);
    Xt[d4 + 0][r] = v.x;
    Xt[d4 + 1][r] = v.y;
    Xt[d4 + 2][r] = v.z;
    Xt[d4 + 3][r] = v.w;
  }

  // persistent f accumulators: 2 rows x 4 cols as packed f32x2 (zero bits == {0.f,0.f})
  u64 f00 = 0ull, f01 = 0ull, f10 = 0ull, f11 = 0ull;

  __syncthreads();

  for (int bt = 0; bt < BAS / BK; bt++) {
    const int b0 = bt * BK;

    // ---- stage St tile: 64 d-rows x 32 basis (2048 floats) ----
    #pragma unroll
    for (int i = 0; i < 2; i++) {
      int j   = tid + i * 256;        // 0..511
      int d   = j >> 3;               // 0..63
      int bb4 = (j & 7) * 4;
      *reinterpret_cast<float4*>(&St[d][bb4]) =
          *reinterpret_cast<const float4*>(&g_St[d * BAS + b0 + bb4]);
    }
    // ---- stage W tile: 64 k-rows x 64 cols (4096 floats) ----
    #pragma unroll
    for (int i = 0; i < 4; i++) {
      int j  = tid + i * 256;         // 0..1023
      int kk = j >> 4;                // 0..63
      int c4 = (j & 15) * 4;
      const float* src = (kk < BK) ? &g_WS[(size_t)(b0 + kk) * DD + c4]
                                   : &g_WC[(size_t)(b0 + kk - BK) * DD + c4];
      *reinterpret_cast<float4*>(&Wsm[kk][c4]) = *reinterpret_cast<const float4*>(src);
    }
    __syncthreads();

    // ---- GEMM1: a[r][b] = sum_d Xt[d][r] * St[d][b]  (2 rows x 2 basis / thread) ----
    u64 a0 = 0ull, a1 = 0ull;
    #pragma unroll
    for (int k = 0; k < DD; k++) {
      u64   s2 = *reinterpret_cast<const u64*>(&St[k][2 * tx]);
      float2 x2 = *reinterpret_cast<const float2*>(&Xt[k][2 * ty]);
      a0 = fma2(pack2(x2.x, x2.x), s2, a0);
      a1 = fma2(pack2(x2.y, x2.y), s2, a1);
    }

    // ---- sincos(pi * a) with exact mod-2 reduction; write transposed into Pt ----
    {
      float d00, d01, d10, d11;
      unpack2(a0, d00, d01);
      unpack2(a1, d10, d11);
      float s00, c00, s01, c01, s10, c10, s11, c11;
      {
        float ar;
        ar = fmaf(-2.0f, rintf(d00 * 0.5f), d00); __sincosf(ar * PI_F, &s00, &c00);
        ar = fmaf(-2.0f, rintf(d01 * 0.5f), d01); __sincosf(ar * PI_F, &s01, &c01);
        ar = fmaf(-2.0f, rintf(d10 * 0.5f), d10); __sincosf(ar * PI_F, &s10, &c10);
        ar = fmaf(-2.0f, rintf(d11 * 0.5f), d11); __sincosf(ar * PI_F, &s11, &c11);
      }
      *reinterpret_cast<u64*>(&Pt[2 * tx    ][2 * ty]) = pack2(s00, s10);
      *reinterpret_cast<u64*>(&Pt[2 * tx + 1][2 * ty]) = pack2(s01, s11);
      *reinterpret_cast<u64*>(&Pt[BK + 2 * tx    ][2 * ty]) = pack2(c00, c10);
      *reinterpret_cast<u64*>(&Pt[BK + 2 * tx + 1][2 * ty]) = pack2(c01, c11);
    }
    __syncthreads();

    // ---- GEMM2: f[r][c] += sum_k Pt[k][r] * Wsm[k][c]  (2 rows x 4 cols / thread) ----
    #pragma unroll
    for (int k = 0; k < 2 * BK; k++) {
      float2     p2 = *reinterpret_cast<const float2*>(&Pt[k][2 * ty]);
      ulonglong2 w2 = *reinterpret_cast<const ulonglong2*>(&Wsm[k][4 * tx]);
      u64 pa = pack2(p2.x, p2.x);
      u64 pb = pack2(p2.y, p2.y);
      f00 = fma2(pa, w2.x, f00);
      f01 = fma2(pa, w2.y, f01);
      f10 = fma2(pb, w2.x, f10);
      f11 = fma2(pb, w2.y, f11);
    }
    __syncthreads();
  }

  // ---- epilogue: write f (coalesced float4 per row) ----
  {
    float o00, o01, o02, o03, o10, o11, o12, o13;
    unpack2(f00, o00, o01); unpack2(f01, o02, o03);
    unpack2(f10, o10, o11); unpack2(f11, o12, o13);
    int r = r0 + 2 * ty;
    int c = 4 * tx;
    *reinterpret_cast<float4*>(&out[(size_t)r * DD + c])       = make_float4(o00, o01, o02, o03);
    *reinterpret_cast<float4*>(&out[(size_t)(r + 1) * DD + c]) = make_float4(o10, o11, o12, o13);
  }
}

extern "C" void kernel_launch(void* const* d_in, const int* in_sizes, int n_in,
                              void* d_out, int out_size) {
  // inputs (metadata order): t, x, epsilon, lam, eta, w
  const float* x_in  = (const float*)d_in[1];
  const float* eps   = (const float*)d_in[2];
  const float* lam   = (const float*)d_in[3];
  const float* eta   = (const float*)d_in[4];
  const float* w     = (const float*)d_in[5];
  float* out = (float*)d_out;

  precompute_kernel<<<(BAS * DD + 255) / 256, 256>>>(eps, lam, eta, w);
  ssgp_main_kernel<<<NROWS / ROWS, THREADS>>>(x_in, out);
}